// round 15
// baseline (speedup 1.0000x reference)
#include <cuda_runtime.h>
#include <cuda_bf16.h>
#include <math.h>

// Shapes (fixed for this problem)
#define NB    4
#define NQ    300
#define NROW  1200     // NB*NQ
#define NWL   8
#define NH    64
#define NW    64
#define ND    256
#define NM    4

// Scratch (device globals — no allocation allowed)
__device__ float  g_AGG[NROW * ND];        // aggregated sampled features
__device__ float  g_H  [NROW * ND];        // ln2(out)
__device__ float  g_G  [NROW * 4 * ND];    // gelu(H @ w_ffn1 + b1)
__device__ float  g_Wc [64 * 16];          // w_rel @ [w_delta_bot | w_alpha_bot]
__device__ float  g_bc [16];               // combined bias
__device__ float  g_STATS[NROW * 2];       // per-row (sum, sumsq) of `out`

// PDL: wait until the predecessor grid's memory is visible. No-op when the
// kernel is launched without the programmatic-stream-serialization attribute.
__device__ __forceinline__ void grid_dep_wait() {
    asm volatile("griddepcontrol.wait;" ::: "memory");
}

__device__ __forceinline__ float fast_tanh(float x) {
    float e = __expf(2.f * x);
    return (e - 1.f) / (e + 1.f);
}

// ---------------------------------------------------------------------------
// block-wide paired sum over 256 threads (deterministic)
__device__ __forceinline__ float2 blockReduce256v2(float a, float b, float2* sred) {
#pragma unroll
    for (int o = 16; o > 0; o >>= 1) {
        a += __shfl_xor_sync(0xffffffffu, a, o);
        b += __shfl_xor_sync(0xffffffffu, b, o);
    }
    int lane = threadIdx.x & 31, w = threadIdx.x >> 5;
    __syncthreads();
    if (lane == 0) sred[w] = make_float2(a, b);
    __syncthreads();
    float sa = 0.f, sb = 0.f;
#pragma unroll
    for (int i = 0; i < 8; i++) { sa += sred[i].x; sb += sred[i].y; }
    return make_float2(sa, sb);
}

// 16B async copy, zero-fill when !pred
__device__ __forceinline__ void cpa16(unsigned saddr, const void* gptr, bool pred) {
    asm volatile("cp.async.cg.shared.global [%0], [%1], 16, %2;"
                 :: "r"(saddr), "l"(gptr), "r"(pred ? 16 : 0));
}

// ---------------------------------------------------------------------------
// Precompute Wcomb[p][j] = sum_k w_rel[p,k] * Wbot[k][j]  (p<64) and
// bcomb[j] = b_delta/b_alpha[j] + sum_k b_rel[k] * Wbot[k][j]  (block 64)
__global__ void __launch_bounds__(256) precomp_kernel(
    const float* __restrict__ w_rel, const float* __restrict__ b_rel,
    const float* __restrict__ w_delta, const float* __restrict__ b_delta,
    const float* __restrict__ w_alpha, const float* __restrict__ b_alpha,
    float* __restrict__ Wc, float* __restrict__ bc)
{
    __shared__ float sp[256][17];
    int p = blockIdx.x;            // 0..63 -> Wcomb row, 64 -> bias row
    int tid = threadIdx.x;
    float a = (p < 64) ? w_rel[p * 256 + tid] : b_rel[tid];
#pragma unroll
    for (int j = 0; j < 12; j++) sp[tid][j] = a * w_delta[(256 + tid) * 12 + j];
#pragma unroll
    for (int j = 0; j < 4; j++)  sp[tid][12 + j] = a * w_alpha[(256 + tid) * 4 + j];
    __syncthreads();
    for (int s = 128; s > 0; s >>= 1) {
        if (tid < s) {
#pragma unroll
            for (int j = 0; j < 16; j++) sp[tid][j] += sp[tid + s][j];
        }
        __syncthreads();
    }
    if (tid < 16) {
        if (p < 64) Wc[p * 16 + tid] = sp[0][tid];
        else        bc[tid] = sp[0][tid] + ((tid < 12) ? b_delta[tid] : b_alpha[tid - 12]);
    }
}

// ---------------------------------------------------------------------------
// Fused deform kernel: one CTA per (b,q) row. LN1/ref/PE run BEFORE the
// grid-dependency wait; Wc/bc staging (precomp outputs) comes after.
// Also zeroes the LN2 stats slot for this row.
__global__ void __launch_bounds__(256) deform_kernel(
    const float* __restrict__ q, const float4* __restrict__ feats4,
    const unsigned char* __restrict__ kmask, const float* __restrict__ ds,
    const float* __restrict__ w_ref, const float* __restrict__ b_ref,
    const float* __restrict__ w_delta, const float* __restrict__ w_alpha,
    const float* __restrict__ lam,
    const float* __restrict__ ln1g, const float* __restrict__ ln1b,
    const float* __restrict__ Wc, const float* __restrict__ bc,
    float4* __restrict__ AGG4, float* __restrict__ stats)
{
    int row = blockIdx.x;                 // 0..1199
    int b   = row / NQ;
    int tid = threadIdx.x;

    __shared__ float2 s_red2[8];
    __shared__ float s_ref[2];
    __shared__ float s_ds[NWL];
    __shared__ float s_pe[NWL][64];
    __shared__ float s_Wc[64][17];
    __shared__ float s_qn[256];
    __shared__ float s_p16[16][17];
    __shared__ float s_top[16];
    __shared__ float s_dl[NWL][16];
    __shared__ float s_wt[NWL][NM];
    __shared__ float s_tan[NWL][12];
    __shared__ float s_samp[32][10];
    __shared__ int   h_key[512];
    __shared__ float h_val[512];
    __shared__ float2 s_pair[256];
    __shared__ float4 s_acc[4][64];
    __shared__ int   s_ws[8], s_wp[8], s_cnt;

    // zero LN2 stats for this row (runs strictly before proj)
    if (tid < 2) stats[row * 2 + tid] = 0.f;

    // init hash table
    h_key[tid] = -1; h_key[tid + 256] = -1;
    h_val[tid] = 0.f; h_val[tid + 256] = 0.f;

    // ---- LN1 (fused mean/var reduction) — inputs only ----
    float qv = q[row * ND + tid];
    float2 mv = blockReduce256v2(qv, qv * qv, s_red2);
    float mean = mv.x * (1.f / 256.f);
    float var  = mv.y * (1.f / 256.f) - mean * mean;
    float qn   = (qv - mean) * rsqrtf(var + 1e-5f) * ln1g[tid] + ln1b[tid];
    s_qn[tid] = qn;

    // ---- reference point: sigmoid(qn @ w_ref + b_ref) — inputs only ----
    float2 rr = blockReduce256v2(qn * w_ref[2 * tid + 0], qn * w_ref[2 * tid + 1], s_red2);
    if (tid == 0) {
        s_ref[0] = 1.f / (1.f + expf(-(rr.x + b_ref[0])));
        s_ref[1] = 1.f / (1.f + expf(-(rr.y + b_ref[1])));
    }
    if (tid < NWL) s_ds[tid] = ds[row * NWL + tid];

    // sinusoidal PE for all 8 windows — inputs only
    for (int e = tid; e < NWL * 64; e += 256) {
        int w = e >> 6, p = e & 63;
        float t = ds[row * NWL + w];
        float v;
        if (p < 32) v = __sinf(t * __expf(-0.28782313662425575f * (float)p));
        else        v = __cosf(t * __expf(-0.28782313662425575f * (float)(p - 32)));
        s_pe[w][p] = v;
    }

    // ---- wait for precomp (Wc, bc), then stage Wc ----
    grid_dep_wait();
    for (int e = tid; e < 64 * 16; e += 256) s_Wc[e >> 4][e & 15] = Wc[e];
    __syncthreads();   // s_qn + s_pe + s_Wc ready

    // ---- top[j] = qn @ Wtop[:,j]: thread=(c,j), 16 FMA each ----
    {
        int j = tid & 15, c = tid >> 4;
        float acc = 0.f;
        if (j < 12) {
#pragma unroll
            for (int i = 0; i < 16; i++) {
                int k = c * 16 + i;
                acc = fmaf(s_qn[k], w_delta[k * 12 + j], acc);
            }
        } else {
            int ja = j - 12;
#pragma unroll
            for (int i = 0; i < 16; i++) {
                int k = c * 16 + i;
                acc = fmaf(s_qn[k], w_alpha[k * 4 + ja], acc);
            }
        }
        s_p16[c][j] = acc;
    }
    __syncthreads();
    if (tid < 16) {
        float a = 0.f;
#pragma unroll
        for (int c = 0; c < 16; c++) a += s_p16[c][tid];
        s_top[tid] = a;
    }
    __syncthreads();

    // ---- per-window delta/logits: dl[w][j] = top[j] + pe_w @ Wc[:,j] + bc[j] ----
    if (tid < 128) {
        int w = tid >> 4, j = tid & 15;
        float acc = s_top[j] + bc[j];
#pragma unroll
        for (int p = 0; p < 64; p++) acc = fmaf(s_pe[w][p], s_Wc[p][j], acc);
        s_dl[w][j] = acc;
    }
    __syncthreads();

    // ---- softmax weights + tanh precompute ----
    if (tid < NWL) {
        float sp  = log1pf(expf(lam[0]));
        float pen = sp * fabsf(s_ds[tid]);
        float z0 = s_dl[tid][12] - pen, z1 = s_dl[tid][13] - pen;
        float z2 = s_dl[tid][14] - pen, z3 = s_dl[tid][15] - pen;
        float mx = fmaxf(fmaxf(z0, z1), fmaxf(z2, z3));
        float e0 = expf(z0 - mx), e1 = expf(z1 - mx), e2 = expf(z2 - mx), e3 = expf(z3 - mx);
        float inv = 1.f / (e0 + e1 + e2 + e3);
        s_wt[tid][0] = e0 * inv; s_wt[tid][1] = e1 * inv;
        s_wt[tid][2] = e2 * inv; s_wt[tid][3] = e3 * inv;
    }
    if (tid >= 32 && tid < 128) {
        int t2 = tid - 32;
        int w = t2 / 12, j = t2 % 12;
        s_tan[w][j] = fast_tanh(s_dl[w][j]);
    }
    __syncthreads();

    // ---- per-(w,m) sampling parameters (threads 0..31) ----
    if (tid < 32) {
        int w = tid >> 2, m = tid & 3;
        float cx = fminf(fmaxf(s_ref[0] + s_tan[w][m * 3 + 0], 0.f), 1.f);
        float cy = fminf(fmaxf(s_ref[1] + s_tan[w][m * 3 + 1], 0.f), 1.f);
        float dt = s_tan[w][m * 3 + 2];
        float target = (float)w + dt;
        float t0f = fminf(fmaxf(floorf(target), 0.f), (float)(NWL - 1));
        float t1f = fminf(t0f + 1.f, (float)(NWL - 1));
        float alpha = target - t0f;
        float px = cx * (float)NW - 0.5f, py = cy * (float)NH - 0.5f;
        float x0f = floorf(px), y0f = floorf(py);
        s_samp[tid][0] = __int_as_float(min(max((int)x0f, 0), NW - 1));
        s_samp[tid][1] = __int_as_float(min(max((int)x0f + 1, 0), NW - 1));
        s_samp[tid][2] = px - x0f;
        s_samp[tid][3] = __int_as_float(min(max((int)y0f, 0), NH - 1));
        s_samp[tid][4] = __int_as_float(min(max((int)y0f + 1, 0), NH - 1));
        s_samp[tid][5] = py - y0f;
        s_samp[tid][6] = __int_as_float((int)t0f);
        s_samp[tid][7] = __int_as_float((int)t1f);
        s_samp[tid][8] = alpha;
        s_samp[tid][9] = s_wt[w][m];
    }
    __syncthreads();

    // ---- build (cell, weight) pair and insert into dedup hash ----
    {
        int s = tid >> 3, c = tid & 7;
        int   x  = __float_as_int(s_samp[s][(c & 1) ? 1 : 0]);
        float wxv = s_samp[s][2];
        float wxc = (c & 1) ? wxv : (1.f - wxv);
        int   y  = __float_as_int(s_samp[s][(c & 2) ? 4 : 3]);
        float wyv = s_samp[s][5];
        float wyc = (c & 2) ? wyv : (1.f - wyv);
        int   t  = __float_as_int(s_samp[s][(c & 4) ? 7 : 6]);
        float al = s_samp[s][8];
        float twc = (c & 4) ? al : (1.f - al);
        float wgt = s_samp[s][9];

        int cell = ((b * NWL + t) * NH + y) * NW + x;
        float wfin = wgt * twc * wyc * wxc;
        if (kmask[cell]) wfin = 0.f;

        unsigned h = (((unsigned)cell * 2654435761u) >> 23) & 511u;
        while (true) {
            int prev = atomicCAS(&h_key[h], -1, cell);
            if (prev == -1 || prev == cell) { atomicAdd(&h_val[h], wfin); break; }
            h = (h + 1) & 511u;
        }
    }
    __syncthreads();

    // ---- compact occupied slots ----
    {
        int k0 = h_key[2 * tid], k1 = h_key[2 * tid + 1];
        int c0 = (k0 != -1) ? 1 : 0, c1 = (k1 != -1) ? 1 : 0;
        int cnt = c0 + c1;
        int lane = tid & 31, wid = tid >> 5;
        int scan = cnt;
#pragma unroll
        for (int o = 1; o < 32; o <<= 1) {
            int t = __shfl_up_sync(0xffffffffu, scan, o);
            if (lane >= o) scan += t;
        }
        if (lane == 31) s_ws[wid] = scan;
        __syncthreads();
        if (tid == 0) {
            int acc = 0;
#pragma unroll
            for (int w = 0; w < 8; w++) { s_wp[w] = acc; acc += s_ws[w]; }
            s_cnt = acc;
        }
        __syncthreads();
        int pos = s_wp[wid] + scan - cnt;
        if (c0) { s_pair[pos] = make_float2(__int_as_float(k0), h_val[2 * tid]); pos++; }
        if (c1) { s_pair[pos] = make_float2(__int_as_float(k1), h_val[2 * tid + 1]); }
    }
    __syncthreads();

    // ---- gather unique cells: 64 channel-quads x 4 groups, 2-way ILP ----
    int n  = s_cnt;
    int cq = tid & 63;
    int g  = tid >> 6;

    float4 acc = make_float4(0.f, 0.f, 0.f, 0.f);
    int i = g;
    for (; i + 4 < n; i += 8) {
        float2 pa = s_pair[i];
        float2 pb = s_pair[i + 4];
        int   offa = __float_as_int(pa.x);
        int   offb = __float_as_int(pb.x);
        float4 va = feats4[offa * 64 + cq];
        float4 vb = feats4[offb * 64 + cq];
        float wa = pa.y, wb = pb.y;
        acc.x = fmaf(wa, va.x, acc.x); acc.y = fmaf(wa, va.y, acc.y);
        acc.z = fmaf(wa, va.z, acc.z); acc.w = fmaf(wa, va.w, acc.w);
        acc.x = fmaf(wb, vb.x, acc.x); acc.y = fmaf(wb, vb.y, acc.y);
        acc.z = fmaf(wb, vb.z, acc.z); acc.w = fmaf(wb, vb.w, acc.w);
    }
    if (i < n) {
        float2 pa = s_pair[i];
        int   offa = __float_as_int(pa.x);
        float4 va = feats4[offa * 64 + cq];
        float wa = pa.y;
        acc.x = fmaf(wa, va.x, acc.x); acc.y = fmaf(wa, va.y, acc.y);
        acc.z = fmaf(wa, va.z, acc.z); acc.w = fmaf(wa, va.w, acc.w);
    }
    s_acc[g][cq] = acc;
    __syncthreads();
    if (g == 0) {
        float4 a0 = s_acc[0][cq], a1 = s_acc[1][cq], a2 = s_acc[2][cq], a3 = s_acc[3][cq];
        float4 t;
        t.x = (a0.x + a1.x) + (a2.x + a3.x);
        t.y = (a0.y + a1.y) + (a2.y + a3.y);
        t.z = (a0.z + a1.z) + (a2.z + a3.z);
        t.w = (a0.w + a1.w) + (a2.w + a3.w);
        AGG4[row * 64 + cq] = t;
    }
}

// ---------------------------------------------------------------------------
// LN2, reduction-free: stats (sum, sumsq) from proj's epilogue. Pure
// elementwise, 2 float4s per thread (independent rows -> 2 load chains).
__global__ void __launch_bounds__(256) ln2_kernel(
    const float4* __restrict__ out4, const float4* __restrict__ g4,
    const float4* __restrict__ b4, const float* __restrict__ stats,
    float4* __restrict__ H4)
{
    int base = blockIdx.x * 512 + threadIdx.x;
    grid_dep_wait();
#pragma unroll
    for (int rep = 0; rep < 2; rep++) {
        int idx = base + rep * 256;
        int row = idx >> 6;
        int col = idx & 63;
        float sm = stats[2 * row], ss = stats[2 * row + 1];
        float mu = sm * (1.f / 256.f);
        float rs = rsqrtf(ss * (1.f / 256.f) - mu * mu + 1e-5f);
        float4 v = out4[idx];
        float4 ga = g4[col], ba = b4[col];
        float4 r;
        r.x = (v.x - mu) * rs * ga.x + ba.x;
        r.y = (v.y - mu) * rs * ga.y + ba.y;
        r.z = (v.z - mu) * rs * ga.z + ba.z;
        r.w = (v.w - mu) * rs * ga.w + ba.w;
        H4[idx] = r;
    }
}

// ---------------------------------------------------------------------------
// TF32 tensor-core GEMM, cp.async 3-stage pipeline, PDL-aware prologue.
// CTA tile 16(M) x 64(N), 128 threads (4 warps, warp tile 16x16), BK=32.
// gridDim.z>1: split-K with atomicAdd accumulate (bias only on slice 0).
// STATS: epilogue accumulates per-row (sum, sumsq) of stored values.
#define AS_STRIDE 36
#define BS_STRIDE 72
#define A_TILE_W  (16 * AS_STRIDE)
#define B_TILE_W  (32 * BS_STRIDE)
template<bool GELU, bool ATOMIC, bool RESID, bool STATS>
__global__ void __launch_bounds__(128) tgemm_k(
    const float* __restrict__ A, const float* __restrict__ W,
    const float* __restrict__ bias, const float* __restrict__ resid,
    float* __restrict__ C, int M, int N, int K, int lda,
    float* __restrict__ stats)
{
    __shared__ float As[3 * A_TILE_W];
    __shared__ float Bs[3 * B_TILE_W];

    int tid  = threadIdx.x;
    int m0   = blockIdx.x * 16, n0 = blockIdx.y * 64;
    int k_off = blockIdx.z * K;
    const float* Ab = A + k_off;
    const float* Wb = W + (long)k_off * N;
    int warp = tid >> 5, lane = tid & 31;
    int wn   = warp * 16;
    int g    = lane >> 2, tig = lane & 3;

    unsigned sA = (unsigned)__cvta_generic_to_shared(As);
    unsigned sB = (unsigned)__cvta_generic_to_shared(Bs);

    int amIdx = tid >> 3, akIdx = tid & 7;
    int bkIdx[4], bnIdx[4];
#pragma unroll
    for (int i = 0; i < 4; i++) { int e = tid + i * 128; bkIdx[i] = e >> 4; bnIdx[i] = e & 15; }

    float d[2][4];
#pragma unroll
    for (int nt = 0; nt < 2; nt++)
#pragma unroll
        for (int e = 0; e < 4; e++) d[nt][e] = 0.f;

    int nIter = K / 32;

    auto issueA = [&](int stage, int k0) {
        int gm = m0 + amIdx;
        cpa16(sA + (stage * A_TILE_W + amIdx * AS_STRIDE + akIdx * 4) * 4,
              Ab + (long)gm * lda + k0 + akIdx * 4, gm < M);
    };
    auto issueB = [&](int stage, int k0) {
#pragma unroll
        for (int i = 0; i < 4; i++) {
            int kk = bkIdx[i], nq = bnIdx[i];
            cpa16(sB + (stage * B_TILE_W + kk * BS_STRIDE + nq * 4) * 4,
                  Wb + (long)(k0 + kk) * N + n0 + nq * 4, true);
        }
    };

    // prologue: weights first (independent of predecessor), then wait, then A
    issueB(0, 0);
    issueB(1, 32);
    asm volatile("cp.async.commit_group;");   // G0: B0+B1
    grid_dep_wait();
    issueA(0, 0);
    asm volatile("cp.async.commit_group;");   // G1: A0
    issueA(1, 32);
    asm volatile("cp.async.commit_group;");   // G2: A1

    int cs = 0, ws = 2;
    for (int it = 0; it < nIter; it++) {
        asm volatile("cp.async.wait_group 1;");
        __syncthreads();

        const float* Ac = As + cs * A_TILE_W;
        const float* Bc = Bs + cs * B_TILE_W;
#pragma unroll
        for (int k8 = 0; k8 < 4; k8++) {
            int kb = k8 * 8;
            unsigned afrag[4];
            unsigned bfrag[2][2];
            afrag[0] = __float_as_uint(Ac[(g)     * AS_STRIDE + kb + tig]);
            afrag[1] = __float_as_uint(Ac[(g + 8) * AS_STRIDE + kb + tig]);
            afrag[2] = __float_as_uint(Ac[(g)     * AS_STRIDE + kb + tig + 4]);
            afrag[3] = __float_as_uint(Ac[(g + 8) * AS_STRIDE + kb + tig + 4]);
#pragma unroll
            for (int nt = 0; nt < 2; nt++) {
                int c = wn + nt * 8 + g;
                bfrag[nt][0] = __float_as_uint(Bc[(kb + tig)     * BS_STRIDE + c]);
                bfrag[nt][1] = __float_as_uint(Bc[(kb + tig + 4) * BS_STRIDE + c]);
            }
#pragma unroll
            for (int nt = 0; nt < 2; nt++)
                asm volatile(
                    "mma.sync.aligned.m16n8k8.row.col.f32.tf32.tf32.f32 "
                    "{%0,%1,%2,%3},{%4,%5,%6,%7},{%8,%9},{%0,%1,%2,%3};"
                    : "+f"(d[nt][0]), "+f"(d[nt][1]), "+f"(d[nt][2]), "+f"(d[nt][3])
                    : "r"(afrag[0]), "r"(afrag[1]), "r"(afrag[2]), "r"(afrag[3]),
                      "r"(bfrag[nt][0]), "r"(bfrag[nt][1]));
        }

        if (it + 2 < nIter) {
            int k0 = (it + 2) * 32;
            issueA(ws, k0);
            issueB(ws, k0);
        }
        asm volatile("cp.async.commit_group;");

        cs = (cs == 2) ? 0 : cs + 1;
        ws = (ws == 2) ? 0 : ws + 1;
    }

    // epilogue
    float rsum[2] = {0.f, 0.f}, rsq[2] = {0.f, 0.f};
#pragma unroll
    for (int nt = 0; nt < 2; nt++) {
        int c = n0 + wn + nt * 8 + 2 * tig;
        bool addBias = (!ATOMIC) || (blockIdx.z == 0);
        float b0 = addBias ? bias[c] : 0.f;
        float b1 = addBias ? bias[c + 1] : 0.f;
#pragma unroll
        for (int h = 0; h < 2; h++) {
            int r = m0 + g + h * 8;
            if (r >= M) continue;
            float v0 = d[nt][2 * h + 0] + b0;
            float v1 = d[nt][2 * h + 1] + b1;
            if (RESID) {
                v0 += resid[r * N + c];
                v1 += resid[r * N + c + 1];
            }
            if (GELU) {
                v0 = 0.5f * v0 * (1.f + erff(v0 * 0.70710678118654752f));
                v1 = 0.5f * v1 * (1.f + erff(v1 * 0.70710678118654752f));
            }
            if (STATS) {
                rsum[h] += v0 + v1;
                rsq[h]  += v0 * v0 + v1 * v1;
            }
            if (ATOMIC) {
                atomicAdd(&C[r * N + c],     v0);
                atomicAdd(&C[r * N + c + 1], v1);
            } else {
                *(float2*)(C + r * N + c) = make_float2(v0, v1);
            }
        }
    }
    if (STATS) {
#pragma unroll
        for (int h = 0; h < 2; h++) {
            float s = rsum[h], ss = rsq[h];
            s  += __shfl_xor_sync(0xffffffffu, s, 1);
            ss += __shfl_xor_sync(0xffffffffu, ss, 1);
            s  += __shfl_xor_sync(0xffffffffu, s, 2);
            ss += __shfl_xor_sync(0xffffffffu, ss, 2);
            if (tig == 0) {
                int r = m0 + g + h * 8;
                if (r < M) {
                    atomicAdd(&stats[2 * r],     s);
                    atomicAdd(&stats[2 * r + 1], ss);
                }
            }
        }
    }
}

// ---------------------------------------------------------------------------
extern "C" void kernel_launch(void* const* d_in, const int* in_sizes, int n_in,
                              void* d_out, int out_size)
{
    const float* q       = (const float*)d_in[0];
    const float* feats   = (const float*)d_in[1];
    const unsigned char* kmask = (const unsigned char*)d_in[2];
    const float* ds      = (const float*)d_in[3];
    const float* w_ref   = (const float*)d_in[4];
    const float* b_ref   = (const float*)d_in[5];
    const float* w_delta = (const float*)d_in[6];
    const float* b_delta = (const float*)d_in[7];
    const float* w_alpha = (const float*)d_in[8];
    const float* b_alpha = (const float*)d_in[9];
    const float* lam     = (const float*)d_in[10];
    const float* w_proj  = (const float*)d_in[11];
    const float* b_proj  = (const float*)d_in[12];
    const float* ln1g    = (const float*)d_in[13];
    const float* ln1b    = (const float*)d_in[14];
    const float* ln2g    = (const float*)d_in[15];
    const float* ln2b    = (const float*)d_in[16];
    const float* w_ffn1  = (const float*)d_in[17];
    const float* b_ffn1  = (const float*)d_in[18];
    const float* w_ffn2  = (const float*)d_in[19];
    const float* b_ffn2  = (const float*)d_in[20];
    const float* w_rel   = (const float*)d_in[21];
    const float* b_rel   = (const float*)d_in[22];
    float* out = (float*)d_out;

    float *pAGG, *pH, *pG, *pWc, *pbc, *pStats;
    cudaGetSymbolAddress((void**)&pAGG,   g_AGG);
    cudaGetSymbolAddress((void**)&pH,     g_H);
    cudaGetSymbolAddress((void**)&pG,     g_G);
    cudaGetSymbolAddress((void**)&pWc,    g_Wc);
    cudaGetSymbolAddress((void**)&pbc,    g_bc);
    cudaGetSymbolAddress((void**)&pStats, g_STATS);

    // PDL launch config (programmatic stream serialization)
    cudaLaunchAttribute pdlAttr[1];
    pdlAttr[0].id = cudaLaunchAttributeProgrammaticStreamSerialization;
    pdlAttr[0].val.programmaticStreamSerializationAllowed = 1;
    cudaLaunchConfig_t cfg = {};
    cfg.attrs = pdlAttr;
    cfg.numAttrs = 1;
    cfg.stream = 0;

    // 1) fold w_rel into the delta/alpha projections (normal launch)
    precomp_kernel<<<65, 256>>>(w_rel, b_rel, w_delta, b_delta, w_alpha, b_alpha, pWc, pbc);

    // 2) fused LN1+param+dedup+gather -> AGG[1200,256]; zeroes LN2 stats;
    //    PDL: LN1/ref/PE overlap precomp, wait before consuming Wc/bc.
    cfg.gridDim = dim3(NROW, 1, 1);
    cfg.blockDim = dim3(256, 1, 1);
    cudaLaunchKernelEx(&cfg, deform_kernel,
                       q, (const float4*)feats, kmask, ds, w_ref, b_ref,
                       w_delta, w_alpha, lam, ln1g, ln1b,
                       (const float*)pWc, (const float*)pbc,
                       (float4*)pAGG, pStats);

    // 3) out = q + AGG @ w_proj + b_proj; accumulates per-row LN2 stats;
    //    PDL: prefetch w_proj during deform.
    cfg.gridDim = dim3(75, 4, 1);
    cfg.blockDim = dim3(128, 1, 1);
    cudaLaunchKernelEx(&cfg, tgemm_k<false, false, true, true>,
                       (const float*)pAGG, w_proj, b_proj, q, out,
                       (int)NROW, (int)ND, (int)ND, (int)ND, pStats);

    // 4) H = LN2(out), reduction-free elementwise using stats; PDL launch.
    cfg.gridDim = dim3(150, 1, 1);
    cfg.blockDim = dim3(256, 1, 1);
    cudaLaunchKernelEx(&cfg, ln2_kernel,
                       (const float4*)out, (const float4*)ln2g,
                       (const float4*)ln2b, (const float*)pStats, (float4*)pH);

    // 5) G = gelu(H @ w_ffn1 + b_ffn1); PDL: prefetch w_ffn1 during ln2
    cfg.gridDim = dim3(75, 16, 1);
    cfg.blockDim = dim3(128, 1, 1);
    cudaLaunchKernelEx(&cfg, tgemm_k<true, false, false, false>,
                       (const float*)pH, w_ffn1, b_ffn1, (const float*)nullptr, pG,
                       (int)NROW, (int)(4 * ND), (int)ND, (int)ND, (float*)nullptr);

    // 6) out += G @ w_ffn2 + b_ffn2, split-K x4; PDL: prefetch w_ffn2 slice
    cfg.gridDim = dim3(75, 4, 4);
    cfg.blockDim = dim3(128, 1, 1);
    cudaLaunchKernelEx(&cfg, tgemm_k<false, true, false, false>,
                       (const float*)pG, w_ffn2, b_ffn2, (const float*)nullptr, out,
                       (int)NROW, (int)ND, (int)ND, (int)(4 * ND), (float*)nullptr);
}

// round 16
// speedup vs baseline: 1.0541x; 1.0541x over previous
#include <cuda_runtime.h>
#include <cuda_bf16.h>
#include <math.h>

// Shapes (fixed for this problem)
#define NB    4
#define NQ    300
#define NROW  1200     // NB*NQ
#define NWL   8
#define NH    64
#define NW    64
#define ND    256
#define NM    4

// Scratch (device globals — no allocation allowed)
__device__ float  g_AGG[NROW * ND];        // aggregated sampled features
__device__ float  g_H  [NROW * ND];        // ln2(out)
__device__ float  g_G  [NROW * 4 * ND];    // gelu(H @ w_ffn1 + b1)
__device__ float  g_Wc [64 * 16];          // w_rel @ [w_delta_bot | w_alpha_bot]
__device__ float  g_bc [16];               // combined bias

// PDL: wait until the predecessor grid's memory is visible. No-op when the
// kernel is launched without the programmatic-stream-serialization attribute.
__device__ __forceinline__ void grid_dep_wait() {
    asm volatile("griddepcontrol.wait;" ::: "memory");
}

__device__ __forceinline__ float fast_tanh(float x) {
    float e = __expf(2.f * x);
    return (e - 1.f) / (e + 1.f);
}

// ---------------------------------------------------------------------------
// block-wide paired sum over 256 threads (deterministic)
__device__ __forceinline__ float2 blockReduce256v2(float a, float b, float2* sred) {
#pragma unroll
    for (int o = 16; o > 0; o >>= 1) {
        a += __shfl_xor_sync(0xffffffffu, a, o);
        b += __shfl_xor_sync(0xffffffffu, b, o);
    }
    int lane = threadIdx.x & 31, w = threadIdx.x >> 5;
    __syncthreads();
    if (lane == 0) sred[w] = make_float2(a, b);
    __syncthreads();
    float sa = 0.f, sb = 0.f;
#pragma unroll
    for (int i = 0; i < 8; i++) { sa += sred[i].x; sb += sred[i].y; }
    return make_float2(sa, sb);
}

// 16B async copy, zero-fill when !pred
__device__ __forceinline__ void cpa16(unsigned saddr, const void* gptr, bool pred) {
    asm volatile("cp.async.cg.shared.global [%0], [%1], 16, %2;"
                 :: "r"(saddr), "l"(gptr), "r"(pred ? 16 : 0));
}

// ---------------------------------------------------------------------------
// Precompute Wcomb[p][j] = sum_k w_rel[p,k] * Wbot[k][j]  (p<64) and
// bcomb[j] = b_delta/b_alpha[j] + sum_k b_rel[k] * Wbot[k][j]  (block 64)
__global__ void __launch_bounds__(256) precomp_kernel(
    const float* __restrict__ w_rel, const float* __restrict__ b_rel,
    const float* __restrict__ w_delta, const float* __restrict__ b_delta,
    const float* __restrict__ w_alpha, const float* __restrict__ b_alpha,
    float* __restrict__ Wc, float* __restrict__ bc)
{
    __shared__ float sp[256][17];
    int p = blockIdx.x;            // 0..63 -> Wcomb row, 64 -> bias row
    int tid = threadIdx.x;
    float a = (p < 64) ? w_rel[p * 256 + tid] : b_rel[tid];
#pragma unroll
    for (int j = 0; j < 12; j++) sp[tid][j] = a * w_delta[(256 + tid) * 12 + j];
#pragma unroll
    for (int j = 0; j < 4; j++)  sp[tid][12 + j] = a * w_alpha[(256 + tid) * 4 + j];
    __syncthreads();
    for (int s = 128; s > 0; s >>= 1) {
        if (tid < s) {
#pragma unroll
            for (int j = 0; j < 16; j++) sp[tid][j] += sp[tid + s][j];
        }
        __syncthreads();
    }
    if (tid < 16) {
        if (p < 64) Wc[p * 16 + tid] = sp[0][tid];
        else        bc[tid] = sp[0][tid] + ((tid < 12) ? b_delta[tid] : b_alpha[tid - 12]);
    }
}

// ---------------------------------------------------------------------------
// Fused deform kernel: one CTA per (b,q) row. LN1/ref/PE run BEFORE the
// grid-dependency wait (they read only kernel inputs); Wc/bc staging (the
// precomp outputs) comes after.
__global__ void __launch_bounds__(256) deform_kernel(
    const float* __restrict__ q, const float4* __restrict__ feats4,
    const unsigned char* __restrict__ kmask, const float* __restrict__ ds,
    const float* __restrict__ w_ref, const float* __restrict__ b_ref,
    const float* __restrict__ w_delta, const float* __restrict__ w_alpha,
    const float* __restrict__ lam,
    const float* __restrict__ ln1g, const float* __restrict__ ln1b,
    const float* __restrict__ Wc, const float* __restrict__ bc,
    float4* __restrict__ AGG4)
{
    int row = blockIdx.x;                 // 0..1199
    int b   = row / NQ;
    int tid = threadIdx.x;

    __shared__ float2 s_red2[8];
    __shared__ float s_ref[2];
    __shared__ float s_ds[NWL];
    __shared__ float s_pe[NWL][64];
    __shared__ float s_Wc[64][17];
    __shared__ float s_qn[256];
    __shared__ float s_p16[16][17];
    __shared__ float s_top[16];
    __shared__ float s_dl[NWL][16];
    __shared__ float s_wt[NWL][NM];
    __shared__ float s_tan[NWL][12];
    __shared__ float s_samp[32][10];
    __shared__ int   h_key[512];
    __shared__ float h_val[512];
    __shared__ float2 s_pair[256];
    __shared__ float4 s_acc[4][64];
    __shared__ int   s_ws[8], s_wp[8], s_cnt;

    // init hash table
    h_key[tid] = -1; h_key[tid + 256] = -1;
    h_val[tid] = 0.f; h_val[tid + 256] = 0.f;

    // ---- LN1 (fused mean/var reduction) — inputs only ----
    float qv = q[row * ND + tid];
    float2 mv = blockReduce256v2(qv, qv * qv, s_red2);
    float mean = mv.x * (1.f / 256.f);
    float var  = mv.y * (1.f / 256.f) - mean * mean;
    float qn   = (qv - mean) * rsqrtf(var + 1e-5f) * ln1g[tid] + ln1b[tid];
    s_qn[tid] = qn;

    // ---- reference point: sigmoid(qn @ w_ref + b_ref) — inputs only ----
    float2 rr = blockReduce256v2(qn * w_ref[2 * tid + 0], qn * w_ref[2 * tid + 1], s_red2);
    if (tid == 0) {
        s_ref[0] = 1.f / (1.f + expf(-(rr.x + b_ref[0])));
        s_ref[1] = 1.f / (1.f + expf(-(rr.y + b_ref[1])));
    }
    if (tid < NWL) s_ds[tid] = ds[row * NWL + tid];

    // sinusoidal PE for all 8 windows — inputs only
    for (int e = tid; e < NWL * 64; e += 256) {
        int w = e >> 6, p = e & 63;
        float t = ds[row * NWL + w];
        float v;
        if (p < 32) v = __sinf(t * __expf(-0.28782313662425575f * (float)p));
        else        v = __cosf(t * __expf(-0.28782313662425575f * (float)(p - 32)));
        s_pe[w][p] = v;
    }

    // ---- wait for precomp (Wc, bc), then stage Wc ----
    grid_dep_wait();
    for (int e = tid; e < 64 * 16; e += 256) s_Wc[e >> 4][e & 15] = Wc[e];
    __syncthreads();   // s_qn + s_pe + s_Wc ready

    // ---- top[j] = qn @ Wtop[:,j]: thread=(c,j), 16 FMA each ----
    {
        int j = tid & 15, c = tid >> 4;
        float acc = 0.f;
        if (j < 12) {
#pragma unroll
            for (int i = 0; i < 16; i++) {
                int k = c * 16 + i;
                acc = fmaf(s_qn[k], w_delta[k * 12 + j], acc);
            }
        } else {
            int ja = j - 12;
#pragma unroll
            for (int i = 0; i < 16; i++) {
                int k = c * 16 + i;
                acc = fmaf(s_qn[k], w_alpha[k * 4 + ja], acc);
            }
        }
        s_p16[c][j] = acc;
    }
    __syncthreads();
    if (tid < 16) {
        float a = 0.f;
#pragma unroll
        for (int c = 0; c < 16; c++) a += s_p16[c][tid];
        s_top[tid] = a;
    }
    __syncthreads();

    // ---- per-window delta/logits: dl[w][j] = top[j] + pe_w @ Wc[:,j] + bc[j] ----
    if (tid < 128) {
        int w = tid >> 4, j = tid & 15;
        float acc = s_top[j] + bc[j];
#pragma unroll
        for (int p = 0; p < 64; p++) acc = fmaf(s_pe[w][p], s_Wc[p][j], acc);
        s_dl[w][j] = acc;
    }
    __syncthreads();

    // ---- softmax weights + tanh precompute ----
    if (tid < NWL) {
        float sp  = log1pf(expf(lam[0]));
        float pen = sp * fabsf(s_ds[tid]);
        float z0 = s_dl[tid][12] - pen, z1 = s_dl[tid][13] - pen;
        float z2 = s_dl[tid][14] - pen, z3 = s_dl[tid][15] - pen;
        float mx = fmaxf(fmaxf(z0, z1), fmaxf(z2, z3));
        float e0 = expf(z0 - mx), e1 = expf(z1 - mx), e2 = expf(z2 - mx), e3 = expf(z3 - mx);
        float inv = 1.f / (e0 + e1 + e2 + e3);
        s_wt[tid][0] = e0 * inv; s_wt[tid][1] = e1 * inv;
        s_wt[tid][2] = e2 * inv; s_wt[tid][3] = e3 * inv;
    }
    if (tid >= 32 && tid < 128) {
        int t2 = tid - 32;
        int w = t2 / 12, j = t2 % 12;
        s_tan[w][j] = fast_tanh(s_dl[w][j]);
    }
    __syncthreads();

    // ---- per-(w,m) sampling parameters (threads 0..31) ----
    if (tid < 32) {
        int w = tid >> 2, m = tid & 3;
        float cx = fminf(fmaxf(s_ref[0] + s_tan[w][m * 3 + 0], 0.f), 1.f);
        float cy = fminf(fmaxf(s_ref[1] + s_tan[w][m * 3 + 1], 0.f), 1.f);
        float dt = s_tan[w][m * 3 + 2];
        float target = (float)w + dt;
        float t0f = fminf(fmaxf(floorf(target), 0.f), (float)(NWL - 1));
        float t1f = fminf(t0f + 1.f, (float)(NWL - 1));
        float alpha = target - t0f;
        float px = cx * (float)NW - 0.5f, py = cy * (float)NH - 0.5f;
        float x0f = floorf(px), y0f = floorf(py);
        s_samp[tid][0] = __int_as_float(min(max((int)x0f, 0), NW - 1));
        s_samp[tid][1] = __int_as_float(min(max((int)x0f + 1, 0), NW - 1));
        s_samp[tid][2] = px - x0f;
        s_samp[tid][3] = __int_as_float(min(max((int)y0f, 0), NH - 1));
        s_samp[tid][4] = __int_as_float(min(max((int)y0f + 1, 0), NH - 1));
        s_samp[tid][5] = py - y0f;
        s_samp[tid][6] = __int_as_float((int)t0f);
        s_samp[tid][7] = __int_as_float((int)t1f);
        s_samp[tid][8] = alpha;
        s_samp[tid][9] = s_wt[w][m];
    }
    __syncthreads();

    // ---- build (cell, weight) pair and insert into dedup hash ----
    {
        int s = tid >> 3, c = tid & 7;
        int   x  = __float_as_int(s_samp[s][(c & 1) ? 1 : 0]);
        float wxv = s_samp[s][2];
        float wxc = (c & 1) ? wxv : (1.f - wxv);
        int   y  = __float_as_int(s_samp[s][(c & 2) ? 4 : 3]);
        float wyv = s_samp[s][5];
        float wyc = (c & 2) ? wyv : (1.f - wyv);
        int   t  = __float_as_int(s_samp[s][(c & 4) ? 7 : 6]);
        float al = s_samp[s][8];
        float twc = (c & 4) ? al : (1.f - al);
        float wgt = s_samp[s][9];

        int cell = ((b * NWL + t) * NH + y) * NW + x;
        float wfin = wgt * twc * wyc * wxc;
        if (kmask[cell]) wfin = 0.f;

        unsigned h = (((unsigned)cell * 2654435761u) >> 23) & 511u;
        while (true) {
            int prev = atomicCAS(&h_key[h], -1, cell);
            if (prev == -1 || prev == cell) { atomicAdd(&h_val[h], wfin); break; }
            h = (h + 1) & 511u;
        }
    }
    __syncthreads();

    // ---- compact occupied slots ----
    {
        int k0 = h_key[2 * tid], k1 = h_key[2 * tid + 1];
        int c0 = (k0 != -1) ? 1 : 0, c1 = (k1 != -1) ? 1 : 0;
        int cnt = c0 + c1;
        int lane = tid & 31, wid = tid >> 5;
        int scan = cnt;
#pragma unroll
        for (int o = 1; o < 32; o <<= 1) {
            int t = __shfl_up_sync(0xffffffffu, scan, o);
            if (lane >= o) scan += t;
        }
        if (lane == 31) s_ws[wid] = scan;
        __syncthreads();
        if (tid == 0) {
            int acc = 0;
#pragma unroll
            for (int w = 0; w < 8; w++) { s_wp[w] = acc; acc += s_ws[w]; }
            s_cnt = acc;
        }
        __syncthreads();
        int pos = s_wp[wid] + scan - cnt;
        if (c0) { s_pair[pos] = make_float2(__int_as_float(k0), h_val[2 * tid]); pos++; }
        if (c1) { s_pair[pos] = make_float2(__int_as_float(k1), h_val[2 * tid + 1]); }
    }
    __syncthreads();

    // ---- gather unique cells: 64 channel-quads x 4 groups ----
    int n  = s_cnt;
    int cq = tid & 63;
    int g  = tid >> 6;

    float4 acc = make_float4(0.f, 0.f, 0.f, 0.f);
#pragma unroll 8
    for (int i = g; i < n; i += 4) {
        float2 p2 = s_pair[i];
        int   off = __float_as_int(p2.x);
        float w   = p2.y;
        float4 v  = feats4[off * 64 + cq];
        acc.x = fmaf(w, v.x, acc.x);
        acc.y = fmaf(w, v.y, acc.y);
        acc.z = fmaf(w, v.z, acc.z);
        acc.w = fmaf(w, v.w, acc.w);
    }
    s_acc[g][cq] = acc;
    __syncthreads();
    if (g == 0) {
        float4 a0 = s_acc[0][cq], a1 = s_acc[1][cq], a2 = s_acc[2][cq], a3 = s_acc[3][cq];
        float4 t;
        t.x = (a0.x + a1.x) + (a2.x + a3.x);
        t.y = (a0.y + a1.y) + (a2.y + a3.y);
        t.z = (a0.z + a1.z) + (a2.z + a3.z);
        t.w = (a0.w + a1.w) + (a2.w + a3.w);
        AGG4[row * 64 + cq] = t;
    }
}

// ---------------------------------------------------------------------------
// LN2: one warp per row, 16 rows per CTA (512 threads). PDL: index math
// before the wait; all loads after.
__global__ void __launch_bounds__(512) ln2_kernel(
    const float* __restrict__ out, const float* __restrict__ g,
    const float* __restrict__ bpar, float* __restrict__ Hbuf)
{
    int wid = threadIdx.x >> 5, lane = threadIdx.x & 31;
    int row = blockIdx.x * 16 + wid;
    const float4* o4 = (const float4*)out + row * 64;
    grid_dep_wait();
    float4 v0 = o4[lane * 2], v1 = o4[lane * 2 + 1];
    float s = (v0.x + v0.y) + (v0.z + v0.w) + (v1.x + v1.y) + (v1.z + v1.w);
#pragma unroll
    for (int o = 16; o > 0; o >>= 1) s += __shfl_xor_sync(0xffffffffu, s, o);
    float mean = s * (1.f / 256.f);
    float d0x = v0.x - mean, d0y = v0.y - mean, d0z = v0.z - mean, d0w = v0.w - mean;
    float d1x = v1.x - mean, d1y = v1.y - mean, d1z = v1.z - mean, d1w = v1.w - mean;
    float sq = (d0x*d0x + d0y*d0y) + (d0z*d0z + d0w*d0w)
             + (d1x*d1x + d1y*d1y) + (d1z*d1z + d1w*d1w);
#pragma unroll
    for (int o = 16; o > 0; o >>= 1) sq += __shfl_xor_sync(0xffffffffu, sq, o);
    float inv = rsqrtf(sq * (1.f / 256.f) + 1e-5f);
    const float4* g4 = (const float4*)g;
    const float4* b4 = (const float4*)bpar;
    float4* H4 = (float4*)Hbuf + row * 64;
    float4 ga = g4[lane * 2], gb = g4[lane * 2 + 1];
    float4 ba = b4[lane * 2], bb = b4[lane * 2 + 1];
    float4 r0, r1;
    r0.x = d0x * inv * ga.x + ba.x; r0.y = d0y * inv * ga.y + ba.y;
    r0.z = d0z * inv * ga.z + ba.z; r0.w = d0w * inv * ga.w + ba.w;
    r1.x = d1x * inv * gb.x + bb.x; r1.y = d1y * inv * gb.y + bb.y;
    r1.z = d1z * inv * gb.z + bb.z; r1.w = d1w * inv * gb.w + bb.w;
    H4[lane * 2]     = r0;
    H4[lane * 2 + 1] = r1;
}

// ---------------------------------------------------------------------------
// TF32 tensor-core GEMM, cp.async 3-stage pipeline, PDL-aware prologue:
// weight (B) loads for stages 0/1 are issued BEFORE griddepcontrol.wait;
// A loads (predecessor output) after. Steady-state wait_group invariant kept.
// CTA tile 16(M) x 64(N), 128 threads (4 warps, warp tile 16x16), BK=32.
// gridDim.z>1: split-K with atomicAdd accumulate (bias only on slice 0).
#define AS_STRIDE 36
#define BS_STRIDE 72
#define A_TILE_W  (16 * AS_STRIDE)
#define B_TILE_W  (32 * BS_STRIDE)
template<bool GELU, bool ATOMIC, bool RESID>
__global__ void __launch_bounds__(128) tgemm_k(
    const float* __restrict__ A, const float* __restrict__ W,
    const float* __restrict__ bias, const float* __restrict__ resid,
    float* __restrict__ C, int M, int N, int K, int lda)
{
    __shared__ float As[3 * A_TILE_W];
    __shared__ float Bs[3 * B_TILE_W];

    int tid  = threadIdx.x;
    int m0   = blockIdx.x * 16, n0 = blockIdx.y * 64;
    int k_off = blockIdx.z * K;
    const float* Ab = A + k_off;
    const float* Wb = W + (long)k_off * N;
    int warp = tid >> 5, lane = tid & 31;
    int wn   = warp * 16;
    int g    = lane >> 2, tig = lane & 3;

    unsigned sA = (unsigned)__cvta_generic_to_shared(As);
    unsigned sB = (unsigned)__cvta_generic_to_shared(Bs);

    int amIdx = tid >> 3, akIdx = tid & 7;
    int bkIdx[4], bnIdx[4];
#pragma unroll
    for (int i = 0; i < 4; i++) { int e = tid + i * 128; bkIdx[i] = e >> 4; bnIdx[i] = e & 15; }

    float d[2][4];
#pragma unroll
    for (int nt = 0; nt < 2; nt++)
#pragma unroll
        for (int e = 0; e < 4; e++) d[nt][e] = 0.f;

    int nIter = K / 32;

    auto issueA = [&](int stage, int k0) {
        int gm = m0 + amIdx;
        cpa16(sA + (stage * A_TILE_W + amIdx * AS_STRIDE + akIdx * 4) * 4,
              Ab + (long)gm * lda + k0 + akIdx * 4, gm < M);
    };
    auto issueB = [&](int stage, int k0) {
#pragma unroll
        for (int i = 0; i < 4; i++) {
            int kk = bkIdx[i], nq = bnIdx[i];
            cpa16(sB + (stage * B_TILE_W + kk * BS_STRIDE + nq * 4) * 4,
                  Wb + (long)(k0 + kk) * N + n0 + nq * 4, true);
        }
    };

    // prologue: weights first (independent of predecessor), then wait, then A
    issueB(0, 0);
    issueB(1, 32);
    asm volatile("cp.async.commit_group;");   // G0: B0+B1
    grid_dep_wait();
    issueA(0, 0);
    asm volatile("cp.async.commit_group;");   // G1: A0
    issueA(1, 32);
    asm volatile("cp.async.commit_group;");   // G2: A1

    int cs = 0, ws = 2;
    for (int it = 0; it < nIter; it++) {
        asm volatile("cp.async.wait_group 1;");
        __syncthreads();

        const float* Ac = As + cs * A_TILE_W;
        const float* Bc = Bs + cs * B_TILE_W;
#pragma unroll
        for (int k8 = 0; k8 < 4; k8++) {
            int kb = k8 * 8;
            unsigned afrag[4];
            unsigned bfrag[2][2];
            afrag[0] = __float_as_uint(Ac[(g)     * AS_STRIDE + kb + tig]);
            afrag[1] = __float_as_uint(Ac[(g + 8) * AS_STRIDE + kb + tig]);
            afrag[2] = __float_as_uint(Ac[(g)     * AS_STRIDE + kb + tig + 4]);
            afrag[3] = __float_as_uint(Ac[(g + 8) * AS_STRIDE + kb + tig + 4]);
#pragma unroll
            for (int nt = 0; nt < 2; nt++) {
                int c = wn + nt * 8 + g;
                bfrag[nt][0] = __float_as_uint(Bc[(kb + tig)     * BS_STRIDE + c]);
                bfrag[nt][1] = __float_as_uint(Bc[(kb + tig + 4) * BS_STRIDE + c]);
            }
#pragma unroll
            for (int nt = 0; nt < 2; nt++)
                asm volatile(
                    "mma.sync.aligned.m16n8k8.row.col.f32.tf32.tf32.f32 "
                    "{%0,%1,%2,%3},{%4,%5,%6,%7},{%8,%9},{%0,%1,%2,%3};"
                    : "+f"(d[nt][0]), "+f"(d[nt][1]), "+f"(d[nt][2]), "+f"(d[nt][3])
                    : "r"(afrag[0]), "r"(afrag[1]), "r"(afrag[2]), "r"(afrag[3]),
                      "r"(bfrag[nt][0]), "r"(bfrag[nt][1]));
        }

        if (it + 2 < nIter) {
            int k0 = (it + 2) * 32;
            issueA(ws, k0);
            issueB(ws, k0);
        }
        asm volatile("cp.async.commit_group;");

        cs = (cs == 2) ? 0 : cs + 1;
        ws = (ws == 2) ? 0 : ws + 1;
    }

    // epilogue
#pragma unroll
    for (int nt = 0; nt < 2; nt++) {
        int c = n0 + wn + nt * 8 + 2 * tig;
        bool addBias = (!ATOMIC) || (blockIdx.z == 0);
        float b0 = addBias ? bias[c] : 0.f;
        float b1 = addBias ? bias[c + 1] : 0.f;
#pragma unroll
        for (int h = 0; h < 2; h++) {
            int r = m0 + g + h * 8;
            if (r >= M) continue;
            float v0 = d[nt][2 * h + 0] + b0;
            float v1 = d[nt][2 * h + 1] + b1;
            if (RESID) {
                v0 += resid[r * N + c];
                v1 += resid[r * N + c + 1];
            }
            if (GELU) {
                v0 = 0.5f * v0 * (1.f + erff(v0 * 0.70710678118654752f));
                v1 = 0.5f * v1 * (1.f + erff(v1 * 0.70710678118654752f));
            }
            if (ATOMIC) {
                atomicAdd(&C[r * N + c],     v0);
                atomicAdd(&C[r * N + c + 1], v1);
            } else {
                *(float2*)(C + r * N + c) = make_float2(v0, v1);
            }
        }
    }
}

// ---------------------------------------------------------------------------
extern "C" void kernel_launch(void* const* d_in, const int* in_sizes, int n_in,
                              void* d_out, int out_size)
{
    const float* q       = (const float*)d_in[0];
    const float* feats   = (const float*)d_in[1];
    const unsigned char* kmask = (const unsigned char*)d_in[2];
    const float* ds      = (const float*)d_in[3];
    const float* w_ref   = (const float*)d_in[4];
    const float* b_ref   = (const float*)d_in[5];
    const float* w_delta = (const float*)d_in[6];
    const float* b_delta = (const float*)d_in[7];
    const float* w_alpha = (const float*)d_in[8];
    const float* b_alpha = (const float*)d_in[9];
    const float* lam     = (const float*)d_in[10];
    const float* w_proj  = (const float*)d_in[11];
    const float* b_proj  = (const float*)d_in[12];
    const float* ln1g    = (const float*)d_in[13];
    const float* ln1b    = (const float*)d_in[14];
    const float* ln2g    = (const float*)d_in[15];
    const float* ln2b    = (const float*)d_in[16];
    const float* w_ffn1  = (const float*)d_in[17];
    const float* b_ffn1  = (const float*)d_in[18];
    const float* w_ffn2  = (const float*)d_in[19];
    const float* b_ffn2  = (const float*)d_in[20];
    const float* w_rel   = (const float*)d_in[21];
    const float* b_rel   = (const float*)d_in[22];
    float* out = (float*)d_out;

    float *pAGG, *pH, *pG, *pWc, *pbc;
    cudaGetSymbolAddress((void**)&pAGG,  g_AGG);
    cudaGetSymbolAddress((void**)&pH,    g_H);
    cudaGetSymbolAddress((void**)&pG,    g_G);
    cudaGetSymbolAddress((void**)&pWc,   g_Wc);
    cudaGetSymbolAddress((void**)&pbc,   g_bc);

    // PDL launch config (programmatic stream serialization)
    cudaLaunchAttribute pdlAttr[1];
    pdlAttr[0].id = cudaLaunchAttributeProgrammaticStreamSerialization;
    pdlAttr[0].val.programmaticStreamSerializationAllowed = 1;
    cudaLaunchConfig_t cfg = {};
    cfg.attrs = pdlAttr;
    cfg.numAttrs = 1;
    cfg.stream = 0;

    // 1) fold w_rel into the delta/alpha projections (normal launch)
    precomp_kernel<<<65, 256>>>(w_rel, b_rel, w_delta, b_delta, w_alpha, b_alpha, pWc, pbc);

    // 2) fused LN1+param+dedup+gather -> AGG[1200,256]; PDL: LN1/ref/PE
    //    overlap precomp, grid_dep_wait before consuming Wc/bc.
    cfg.gridDim = dim3(NROW, 1, 1);
    cfg.blockDim = dim3(256, 1, 1);
    cudaLaunchKernelEx(&cfg, deform_kernel,
                       q, (const float4*)feats, kmask, ds, w_ref, b_ref,
                       w_delta, w_alpha, lam, ln1g, ln1b,
                       (const float*)pWc, (const float*)pbc, (float4*)pAGG);

    // 3) out = q + AGG @ w_proj + b_proj; PDL: prefetch w_proj during deform
    cfg.gridDim = dim3(75, 4, 1);
    cfg.blockDim = dim3(128, 1, 1);
    cudaLaunchKernelEx(&cfg, tgemm_k<false, false, true>,
                       (const float*)pAGG, w_proj, b_proj, q, out,
                       (int)NROW, (int)ND, (int)ND, (int)ND);

    // 4) H = LN2(out); PDL: launch overhead overlaps proj's drain
    cfg.gridDim = dim3(NROW / 16, 1, 1);
    cfg.blockDim = dim3(512, 1, 1);
    cudaLaunchKernelEx(&cfg, ln2_kernel, (const float*)out, ln2g, ln2b, pH);

    // 5) G = gelu(H @ w_ffn1 + b_ffn1); PDL: prefetch w_ffn1 during ln2
    cfg.gridDim = dim3(75, 16, 1);
    cfg.blockDim = dim3(128, 1, 1);
    cudaLaunchKernelEx(&cfg, tgemm_k<true, false, false>,
                       (const float*)pH, w_ffn1, b_ffn1, (const float*)nullptr, pG,
                       (int)NROW, (int)(4 * ND), (int)ND, (int)ND);

    // 6) out += G @ w_ffn2 + b_ffn2, split-K x4; PDL: prefetch w_ffn2 slice
    cfg.gridDim = dim3(75, 4, 4);
    cfg.blockDim = dim3(128, 1, 1);
    cudaLaunchKernelEx(&cfg, tgemm_k<false, true, false>,
                       (const float*)pG, w_ffn2, b_ffn2, (const float*)nullptr, out,
                       (int)NROW, (int)ND, (int)ND, (int)(4 * ND));
}

// round 17
// speedup vs baseline: 1.1154x; 1.0582x over previous
#include <cuda_runtime.h>
#include <cuda_bf16.h>
#include <math.h>

// Shapes (fixed for this problem)
#define NB    4
#define NQ    300
#define NROW  1200     // NB*NQ
#define NWL   8
#define NH    64
#define NW    64
#define ND    256
#define NM    4

// Scratch (device globals — no allocation allowed)
__device__ float  g_AGG[NROW * ND];        // aggregated sampled features
__device__ float  g_H  [NROW * ND];        // ln2(out)
__device__ float  g_G  [NROW * 4 * ND];    // gelu(H @ w_ffn1 + b1)
__device__ float  g_Wc [64 * 16];          // w_rel @ [w_delta_bot | w_alpha_bot]
__device__ float  g_bc [16];               // combined bias

// PDL: wait until the predecessor grid's memory is visible. No-op when the
// kernel is launched without the programmatic-stream-serialization attribute.
__device__ __forceinline__ void grid_dep_wait() {
    asm volatile("griddepcontrol.wait;" ::: "memory");
}

__device__ __forceinline__ float fast_tanh(float x) {
    float e = __expf(2.f * x);
    return (e - 1.f) / (e + 1.f);
}

// ---------------------------------------------------------------------------
// block-wide paired sum over 256 threads (deterministic)
__device__ __forceinline__ float2 blockReduce256v2(float a, float b, float2* sred) {
#pragma unroll
    for (int o = 16; o > 0; o >>= 1) {
        a += __shfl_xor_sync(0xffffffffu, a, o);
        b += __shfl_xor_sync(0xffffffffu, b, o);
    }
    int lane = threadIdx.x & 31, w = threadIdx.x >> 5;
    __syncthreads();
    if (lane == 0) sred[w] = make_float2(a, b);
    __syncthreads();
    float sa = 0.f, sb = 0.f;
#pragma unroll
    for (int i = 0; i < 8; i++) { sa += sred[i].x; sb += sred[i].y; }
    return make_float2(sa, sb);
}

// 16B async copy, zero-fill when !pred
__device__ __forceinline__ void cpa16(unsigned saddr, const void* gptr, bool pred) {
    asm volatile("cp.async.cg.shared.global [%0], [%1], 16, %2;"
                 :: "r"(saddr), "l"(gptr), "r"(pred ? 16 : 0));
}

// ---------------------------------------------------------------------------
// Precompute Wcomb[p][j] = sum_k w_rel[p,k] * Wbot[k][j]  (p<64) and
// bcomb[j] = b_delta/b_alpha[j] + sum_k b_rel[k] * Wbot[k][j]  (block 64)
__global__ void __launch_bounds__(256) precomp_kernel(
    const float* __restrict__ w_rel, const float* __restrict__ b_rel,
    const float* __restrict__ w_delta, const float* __restrict__ b_delta,
    const float* __restrict__ w_alpha, const float* __restrict__ b_alpha,
    float* __restrict__ Wc, float* __restrict__ bc)
{
    __shared__ float sp[256][17];
    int p = blockIdx.x;            // 0..63 -> Wcomb row, 64 -> bias row
    int tid = threadIdx.x;
    float a = (p < 64) ? w_rel[p * 256 + tid] : b_rel[tid];
#pragma unroll
    for (int j = 0; j < 12; j++) sp[tid][j] = a * w_delta[(256 + tid) * 12 + j];
#pragma unroll
    for (int j = 0; j < 4; j++)  sp[tid][12 + j] = a * w_alpha[(256 + tid) * 4 + j];
    __syncthreads();
    for (int s = 128; s > 0; s >>= 1) {
        if (tid < s) {
#pragma unroll
            for (int j = 0; j < 16; j++) sp[tid][j] += sp[tid + s][j];
        }
        __syncthreads();
    }
    if (tid < 16) {
        if (p < 64) Wc[p * 16 + tid] = sp[0][tid];
        else        bc[tid] = sp[0][tid] + ((tid < 12) ? b_delta[tid] : b_alpha[tid - 12]);
    }
}

// ---------------------------------------------------------------------------
// Fused deform kernel: one CTA per (b,q) row. LN1/ref/PE run BEFORE the
// grid-dependency wait (they read only kernel inputs); Wc/bc staging (the
// precomp outputs) comes after.
__global__ void __launch_bounds__(256) deform_kernel(
    const float* __restrict__ q, const float4* __restrict__ feats4,
    const unsigned char* __restrict__ kmask, const float* __restrict__ ds,
    const float* __restrict__ w_ref, const float* __restrict__ b_ref,
    const float* __restrict__ w_delta, const float* __restrict__ w_alpha,
    const float* __restrict__ lam,
    const float* __restrict__ ln1g, const float* __restrict__ ln1b,
    const float* __restrict__ Wc, const float* __restrict__ bc,
    float4* __restrict__ AGG4)
{
    int row = blockIdx.x;                 // 0..1199
    int b   = row / NQ;
    int tid = threadIdx.x;

    __shared__ float2 s_red2[8];
    __shared__ float s_ref[2];
    __shared__ float s_ds[NWL];
    __shared__ float s_pe[NWL][64];
    __shared__ float s_Wc[64][17];
    __shared__ float s_qn[256];
    __shared__ float s_p16[16][17];
    __shared__ float s_top[16];
    __shared__ float s_dl[NWL][16];
    __shared__ float s_wt[NWL][NM];
    __shared__ float s_tan[NWL][12];
    __shared__ float s_samp[32][10];
    __shared__ int   h_key[512];
    __shared__ float h_val[512];
    __shared__ float2 s_pair[256];
    __shared__ float4 s_acc[4][64];
    __shared__ int   s_ws[8], s_wp[8], s_cnt;

    // init hash table
    h_key[tid] = -1; h_key[tid + 256] = -1;
    h_val[tid] = 0.f; h_val[tid + 256] = 0.f;

    // ---- LN1 (fused mean/var reduction) — inputs only ----
    float qv = q[row * ND + tid];
    float2 mv = blockReduce256v2(qv, qv * qv, s_red2);
    float mean = mv.x * (1.f / 256.f);
    float var  = mv.y * (1.f / 256.f) - mean * mean;
    float qn   = (qv - mean) * rsqrtf(var + 1e-5f) * ln1g[tid] + ln1b[tid];
    s_qn[tid] = qn;

    // ---- reference point: sigmoid(qn @ w_ref + b_ref) — inputs only ----
    float2 rr = blockReduce256v2(qn * w_ref[2 * tid + 0], qn * w_ref[2 * tid + 1], s_red2);
    if (tid == 0) {
        s_ref[0] = 1.f / (1.f + expf(-(rr.x + b_ref[0])));
        s_ref[1] = 1.f / (1.f + expf(-(rr.y + b_ref[1])));
    }
    if (tid < NWL) s_ds[tid] = ds[row * NWL + tid];

    // sinusoidal PE for all 8 windows — inputs only
    for (int e = tid; e < NWL * 64; e += 256) {
        int w = e >> 6, p = e & 63;
        float t = ds[row * NWL + w];
        float v;
        if (p < 32) v = __sinf(t * __expf(-0.28782313662425575f * (float)p));
        else        v = __cosf(t * __expf(-0.28782313662425575f * (float)(p - 32)));
        s_pe[w][p] = v;
    }

    // ---- wait for precomp (Wc, bc), then stage Wc ----
    grid_dep_wait();
    for (int e = tid; e < 64 * 16; e += 256) s_Wc[e >> 4][e & 15] = Wc[e];
    __syncthreads();   // s_qn + s_pe + s_Wc ready

    // ---- top[j] = qn @ Wtop[:,j]: thread=(c,j), 16 FMA each ----
    {
        int j = tid & 15, c = tid >> 4;
        float acc = 0.f;
        if (j < 12) {
#pragma unroll
            for (int i = 0; i < 16; i++) {
                int k = c * 16 + i;
                acc = fmaf(s_qn[k], w_delta[k * 12 + j], acc);
            }
        } else {
            int ja = j - 12;
#pragma unroll
            for (int i = 0; i < 16; i++) {
                int k = c * 16 + i;
                acc = fmaf(s_qn[k], w_alpha[k * 4 + ja], acc);
            }
        }
        s_p16[c][j] = acc;
    }
    __syncthreads();
    if (tid < 16) {
        float a = 0.f;
#pragma unroll
        for (int c = 0; c < 16; c++) a += s_p16[c][tid];
        s_top[tid] = a;
    }
    __syncthreads();

    // ---- per-window delta/logits: dl[w][j] = top[j] + pe_w @ Wc[:,j] + bc[j] ----
    if (tid < 128) {
        int w = tid >> 4, j = tid & 15;
        float acc = s_top[j] + bc[j];
#pragma unroll
        for (int p = 0; p < 64; p++) acc = fmaf(s_pe[w][p], s_Wc[p][j], acc);
        s_dl[w][j] = acc;
    }
    __syncthreads();

    // ---- softmax weights + tanh precompute ----
    if (tid < NWL) {
        float sp  = log1pf(expf(lam[0]));
        float pen = sp * fabsf(s_ds[tid]);
        float z0 = s_dl[tid][12] - pen, z1 = s_dl[tid][13] - pen;
        float z2 = s_dl[tid][14] - pen, z3 = s_dl[tid][15] - pen;
        float mx = fmaxf(fmaxf(z0, z1), fmaxf(z2, z3));
        float e0 = expf(z0 - mx), e1 = expf(z1 - mx), e2 = expf(z2 - mx), e3 = expf(z3 - mx);
        float inv = 1.f / (e0 + e1 + e2 + e3);
        s_wt[tid][0] = e0 * inv; s_wt[tid][1] = e1 * inv;
        s_wt[tid][2] = e2 * inv; s_wt[tid][3] = e3 * inv;
    }
    if (tid >= 32 && tid < 128) {
        int t2 = tid - 32;
        int w = t2 / 12, j = t2 % 12;
        s_tan[w][j] = fast_tanh(s_dl[w][j]);
    }
    __syncthreads();

    // ---- per-(w,m) sampling parameters (threads 0..31) ----
    if (tid < 32) {
        int w = tid >> 2, m = tid & 3;
        float cx = fminf(fmaxf(s_ref[0] + s_tan[w][m * 3 + 0], 0.f), 1.f);
        float cy = fminf(fmaxf(s_ref[1] + s_tan[w][m * 3 + 1], 0.f), 1.f);
        float dt = s_tan[w][m * 3 + 2];
        float target = (float)w + dt;
        float t0f = fminf(fmaxf(floorf(target), 0.f), (float)(NWL - 1));
        float t1f = fminf(t0f + 1.f, (float)(NWL - 1));
        float alpha = target - t0f;
        float px = cx * (float)NW - 0.5f, py = cy * (float)NH - 0.5f;
        float x0f = floorf(px), y0f = floorf(py);
        s_samp[tid][0] = __int_as_float(min(max((int)x0f, 0), NW - 1));
        s_samp[tid][1] = __int_as_float(min(max((int)x0f + 1, 0), NW - 1));
        s_samp[tid][2] = px - x0f;
        s_samp[tid][3] = __int_as_float(min(max((int)y0f, 0), NH - 1));
        s_samp[tid][4] = __int_as_float(min(max((int)y0f + 1, 0), NH - 1));
        s_samp[tid][5] = py - y0f;
        s_samp[tid][6] = __int_as_float((int)t0f);
        s_samp[tid][7] = __int_as_float((int)t1f);
        s_samp[tid][8] = alpha;
        s_samp[tid][9] = s_wt[w][m];
    }
    __syncthreads();

    // ---- build (cell, weight) pair and insert into dedup hash ----
    {
        int s = tid >> 3, c = tid & 7;
        int   x  = __float_as_int(s_samp[s][(c & 1) ? 1 : 0]);
        float wxv = s_samp[s][2];
        float wxc = (c & 1) ? wxv : (1.f - wxv);
        int   y  = __float_as_int(s_samp[s][(c & 2) ? 4 : 3]);
        float wyv = s_samp[s][5];
        float wyc = (c & 2) ? wyv : (1.f - wyv);
        int   t  = __float_as_int(s_samp[s][(c & 4) ? 7 : 6]);
        float al = s_samp[s][8];
        float twc = (c & 4) ? al : (1.f - al);
        float wgt = s_samp[s][9];

        int cell = ((b * NWL + t) * NH + y) * NW + x;
        float wfin = wgt * twc * wyc * wxc;
        if (kmask[cell]) wfin = 0.f;

        unsigned h = (((unsigned)cell * 2654435761u) >> 23) & 511u;
        while (true) {
            int prev = atomicCAS(&h_key[h], -1, cell);
            if (prev == -1 || prev == cell) { atomicAdd(&h_val[h], wfin); break; }
            h = (h + 1) & 511u;
        }
    }
    __syncthreads();

    // ---- compact occupied slots ----
    {
        int k0 = h_key[2 * tid], k1 = h_key[2 * tid + 1];
        int c0 = (k0 != -1) ? 1 : 0, c1 = (k1 != -1) ? 1 : 0;
        int cnt = c0 + c1;
        int lane = tid & 31, wid = tid >> 5;
        int scan = cnt;
#pragma unroll
        for (int o = 1; o < 32; o <<= 1) {
            int t = __shfl_up_sync(0xffffffffu, scan, o);
            if (lane >= o) scan += t;
        }
        if (lane == 31) s_ws[wid] = scan;
        __syncthreads();
        if (tid == 0) {
            int acc = 0;
#pragma unroll
            for (int w = 0; w < 8; w++) { s_wp[w] = acc; acc += s_ws[w]; }
            s_cnt = acc;
        }
        __syncthreads();
        int pos = s_wp[wid] + scan - cnt;
        if (c0) { s_pair[pos] = make_float2(__int_as_float(k0), h_val[2 * tid]); pos++; }
        if (c1) { s_pair[pos] = make_float2(__int_as_float(k1), h_val[2 * tid + 1]); }
    }
    __syncthreads();

    // ---- gather unique cells: 64 channel-quads x 4 groups ----
    int n  = s_cnt;
    int cq = tid & 63;
    int g  = tid >> 6;

    float4 acc = make_float4(0.f, 0.f, 0.f, 0.f);
#pragma unroll 8
    for (int i = g; i < n; i += 4) {
        float2 p2 = s_pair[i];
        int   off = __float_as_int(p2.x);
        float w   = p2.y;
        float4 v  = feats4[off * 64 + cq];
        acc.x = fmaf(w, v.x, acc.x);
        acc.y = fmaf(w, v.y, acc.y);
        acc.z = fmaf(w, v.z, acc.z);
        acc.w = fmaf(w, v.w, acc.w);
    }
    s_acc[g][cq] = acc;
    __syncthreads();
    if (g == 0) {
        float4 a0 = s_acc[0][cq], a1 = s_acc[1][cq], a2 = s_acc[2][cq], a3 = s_acc[3][cq];
        float4 t;
        t.x = (a0.x + a1.x) + (a2.x + a3.x);
        t.y = (a0.y + a1.y) + (a2.y + a3.y);
        t.z = (a0.z + a1.z) + (a2.z + a3.z);
        t.w = (a0.w + a1.w) + (a2.w + a3.w);
        AGG4[row * 64 + cq] = t;
    }
}

// ---------------------------------------------------------------------------
// LN2: one warp per row, 16 rows per CTA (512 threads). PDL: index math
// before the wait; all loads after.
__global__ void __launch_bounds__(512) ln2_kernel(
    const float* __restrict__ out, const float* __restrict__ g,
    const float* __restrict__ bpar, float* __restrict__ Hbuf)
{
    int wid = threadIdx.x >> 5, lane = threadIdx.x & 31;
    int row = blockIdx.x * 16 + wid;
    const float4* o4 = (const float4*)out + row * 64;
    grid_dep_wait();
    float4 v0 = o4[lane * 2], v1 = o4[lane * 2 + 1];
    float s = (v0.x + v0.y) + (v0.z + v0.w) + (v1.x + v1.y) + (v1.z + v1.w);
#pragma unroll
    for (int o = 16; o > 0; o >>= 1) s += __shfl_xor_sync(0xffffffffu, s, o);
    float mean = s * (1.f / 256.f);
    float d0x = v0.x - mean, d0y = v0.y - mean, d0z = v0.z - mean, d0w = v0.w - mean;
    float d1x = v1.x - mean, d1y = v1.y - mean, d1z = v1.z - mean, d1w = v1.w - mean;
    float sq = (d0x*d0x + d0y*d0y) + (d0z*d0z + d0w*d0w)
             + (d1x*d1x + d1y*d1y) + (d1z*d1z + d1w*d1w);
#pragma unroll
    for (int o = 16; o > 0; o >>= 1) sq += __shfl_xor_sync(0xffffffffu, sq, o);
    float inv = rsqrtf(sq * (1.f / 256.f) + 1e-5f);
    const float4* g4 = (const float4*)g;
    const float4* b4 = (const float4*)bpar;
    float4* H4 = (float4*)Hbuf + row * 64;
    float4 ga = g4[lane * 2], gb = g4[lane * 2 + 1];
    float4 ba = b4[lane * 2], bb = b4[lane * 2 + 1];
    float4 r0, r1;
    r0.x = d0x * inv * ga.x + ba.x; r0.y = d0y * inv * ga.y + ba.y;
    r0.z = d0z * inv * ga.z + ba.z; r0.w = d0w * inv * ga.w + ba.w;
    r1.x = d1x * inv * gb.x + bb.x; r1.y = d1y * inv * gb.y + bb.y;
    r1.z = d1z * inv * gb.z + bb.z; r1.w = d1w * inv * gb.w + bb.w;
    H4[lane * 2]     = r0;
    H4[lane * 2 + 1] = r1;
}

// ---------------------------------------------------------------------------
// TF32 tensor-core GEMM, cp.async 3-stage pipeline, PDL-aware prologue.
// BM=16 variant: CTA tile 16x64, 128 threads (4 warps, warp tile 16x16).
// gridDim.z>1: split-K with float2 atomicAdd accumulate (bias only slice 0).
#define AS_STRIDE 36
#define BS_STRIDE 72
#define A_TILE_W  (16 * AS_STRIDE)
#define B_TILE_W  (32 * BS_STRIDE)
template<bool GELU, bool ATOMIC, bool RESID>
__global__ void __launch_bounds__(128) tgemm_k(
    const float* __restrict__ A, const float* __restrict__ W,
    const float* __restrict__ bias, const float* __restrict__ resid,
    float* __restrict__ C, int M, int N, int K, int lda)
{
    __shared__ float As[3 * A_TILE_W];
    __shared__ float Bs[3 * B_TILE_W];

    int tid  = threadIdx.x;
    int m0   = blockIdx.x * 16, n0 = blockIdx.y * 64;
    int k_off = blockIdx.z * K;
    const float* Ab = A + k_off;
    const float* Wb = W + (long)k_off * N;
    int warp = tid >> 5, lane = tid & 31;
    int wn   = warp * 16;
    int g    = lane >> 2, tig = lane & 3;

    unsigned sA = (unsigned)__cvta_generic_to_shared(As);
    unsigned sB = (unsigned)__cvta_generic_to_shared(Bs);

    int amIdx = tid >> 3, akIdx = tid & 7;
    int bkIdx[4], bnIdx[4];
#pragma unroll
    for (int i = 0; i < 4; i++) { int e = tid + i * 128; bkIdx[i] = e >> 4; bnIdx[i] = e & 15; }

    float d[2][4];
#pragma unroll
    for (int nt = 0; nt < 2; nt++)
#pragma unroll
        for (int e = 0; e < 4; e++) d[nt][e] = 0.f;

    int nIter = K / 32;

    auto issueA = [&](int stage, int k0) {
        int gm = m0 + amIdx;
        cpa16(sA + (stage * A_TILE_W + amIdx * AS_STRIDE + akIdx * 4) * 4,
              Ab + (long)gm * lda + k0 + akIdx * 4, gm < M);
    };
    auto issueB = [&](int stage, int k0) {
#pragma unroll
        for (int i = 0; i < 4; i++) {
            int kk = bkIdx[i], nq = bnIdx[i];
            cpa16(sB + (stage * B_TILE_W + kk * BS_STRIDE + nq * 4) * 4,
                  Wb + (long)(k0 + kk) * N + n0 + nq * 4, true);
        }
    };

    // prologue: weights first (independent of predecessor), then wait, then A
    issueB(0, 0);
    issueB(1, 32);
    asm volatile("cp.async.commit_group;");   // G0: B0+B1
    grid_dep_wait();
    issueA(0, 0);
    asm volatile("cp.async.commit_group;");   // G1: A0
    issueA(1, 32);
    asm volatile("cp.async.commit_group;");   // G2: A1

    int cs = 0, ws = 2;
    for (int it = 0; it < nIter; it++) {
        asm volatile("cp.async.wait_group 1;");
        __syncthreads();

        const float* Ac = As + cs * A_TILE_W;
        const float* Bc = Bs + cs * B_TILE_W;
#pragma unroll
        for (int k8 = 0; k8 < 4; k8++) {
            int kb = k8 * 8;
            unsigned afrag[4];
            unsigned bfrag[2][2];
            afrag[0] = __float_as_uint(Ac[(g)     * AS_STRIDE + kb + tig]);
            afrag[1] = __float_as_uint(Ac[(g + 8) * AS_STRIDE + kb + tig]);
            afrag[2] = __float_as_uint(Ac[(g)     * AS_STRIDE + kb + tig + 4]);
            afrag[3] = __float_as_uint(Ac[(g + 8) * AS_STRIDE + kb + tig + 4]);
#pragma unroll
            for (int nt = 0; nt < 2; nt++) {
                int c = wn + nt * 8 + g;
                bfrag[nt][0] = __float_as_uint(Bc[(kb + tig)     * BS_STRIDE + c]);
                bfrag[nt][1] = __float_as_uint(Bc[(kb + tig + 4) * BS_STRIDE + c]);
            }
#pragma unroll
            for (int nt = 0; nt < 2; nt++)
                asm volatile(
                    "mma.sync.aligned.m16n8k8.row.col.f32.tf32.tf32.f32 "
                    "{%0,%1,%2,%3},{%4,%5,%6,%7},{%8,%9},{%0,%1,%2,%3};"
                    : "+f"(d[nt][0]), "+f"(d[nt][1]), "+f"(d[nt][2]), "+f"(d[nt][3])
                    : "r"(afrag[0]), "r"(afrag[1]), "r"(afrag[2]), "r"(afrag[3]),
                      "r"(bfrag[nt][0]), "r"(bfrag[nt][1]));
        }

        if (it + 2 < nIter) {
            int k0 = (it + 2) * 32;
            issueA(ws, k0);
            issueB(ws, k0);
        }
        asm volatile("cp.async.commit_group;");

        cs = (cs == 2) ? 0 : cs + 1;
        ws = (ws == 2) ? 0 : ws + 1;
    }

    // epilogue
#pragma unroll
    for (int nt = 0; nt < 2; nt++) {
        int c = n0 + wn + nt * 8 + 2 * tig;
        bool addBias = (!ATOMIC) || (blockIdx.z == 0);
        float b0 = addBias ? bias[c] : 0.f;
        float b1 = addBias ? bias[c + 1] : 0.f;
#pragma unroll
        for (int h = 0; h < 2; h++) {
            int r = m0 + g + h * 8;
            if (r >= M) continue;
            float v0 = d[nt][2 * h + 0] + b0;
            float v1 = d[nt][2 * h + 1] + b1;
            if (RESID) {
                v0 += resid[r * N + c];
                v1 += resid[r * N + c + 1];
            }
            if (GELU) {
                v0 = 0.5f * v0 * (1.f + erff(v0 * 0.70710678118654752f));
                v1 = 0.5f * v1 * (1.f + erff(v1 * 0.70710678118654752f));
            }
            if (ATOMIC) {
                atomicAdd((float2*)(C + r * N + c), make_float2(v0, v1));
            } else {
                *(float2*)(C + r * N + c) = make_float2(v0, v1);
            }
        }
    }
}

// ---------------------------------------------------------------------------
// BM=32 variant (R8 mainloop + PDL prologue): CTA tile 32x64, 128 threads
// (4 warps, warp tile 16x32). Used for ffn1 (halves B re-read traffic).
#define A32_TILE_W (32 * AS_STRIDE)
template<bool GELU>
__global__ void __launch_bounds__(128) tgemm32_k(
    const float* __restrict__ A, const float* __restrict__ W,
    const float* __restrict__ bias, float* __restrict__ C,
    int M, int N, int K, int lda)
{
    __shared__ float As[3 * A32_TILE_W];
    __shared__ float Bs[3 * B_TILE_W];

    int tid  = threadIdx.x;
    int m0   = blockIdx.x * 32, n0 = blockIdx.y * 64;
    int warp = tid >> 5, lane = tid & 31;
    int wm   = (warp & 1) * 16, wn = (warp >> 1) * 32;
    int g    = lane >> 2, tig = lane & 3;

    unsigned sA = (unsigned)__cvta_generic_to_shared(As);
    unsigned sB = (unsigned)__cvta_generic_to_shared(Bs);

    int amIdx[2], akIdx[2];
#pragma unroll
    for (int i = 0; i < 2; i++) { int e = tid + i * 128; amIdx[i] = e >> 3; akIdx[i] = e & 7; }
    int bkIdx[4], bnIdx[4];
#pragma unroll
    for (int i = 0; i < 4; i++) { int e = tid + i * 128; bkIdx[i] = e >> 4; bnIdx[i] = e & 15; }

    float d[4][4];
#pragma unroll
    for (int nt = 0; nt < 4; nt++)
#pragma unroll
        for (int e = 0; e < 4; e++) d[nt][e] = 0.f;

    int nIter = K / 32;

    auto issueA = [&](int stage, int k0) {
#pragma unroll
        for (int i = 0; i < 2; i++) {
            int m = amIdx[i], kq = akIdx[i];
            int gm = m0 + m;
            cpa16(sA + (stage * A32_TILE_W + m * AS_STRIDE + kq * 4) * 4,
                  A + (long)gm * lda + k0 + kq * 4, gm < M);
        }
    };
    auto issueB = [&](int stage, int k0) {
#pragma unroll
        for (int i = 0; i < 4; i++) {
            int kk = bkIdx[i], nq = bnIdx[i];
            cpa16(sB + (stage * B_TILE_W + kk * BS_STRIDE + nq * 4) * 4,
                  W + (long)(k0 + kk) * N + n0 + nq * 4, true);
        }
    };

    issueB(0, 0);
    issueB(1, 32);
    asm volatile("cp.async.commit_group;");   // G0
    grid_dep_wait();
    issueA(0, 0);
    asm volatile("cp.async.commit_group;");   // G1
    issueA(1, 32);
    asm volatile("cp.async.commit_group;");   // G2

    int cs = 0, ws = 2;
    for (int it = 0; it < nIter; it++) {
        asm volatile("cp.async.wait_group 1;");
        __syncthreads();

        const float* Ac = As + cs * A32_TILE_W;
        const float* Bc = Bs + cs * B_TILE_W;
#pragma unroll
        for (int k8 = 0; k8 < 4; k8++) {
            int kb = k8 * 8;
            unsigned afrag[4];
            unsigned bfrag[4][2];
            afrag[0] = __float_as_uint(Ac[(wm + g)     * AS_STRIDE + kb + tig]);
            afrag[1] = __float_as_uint(Ac[(wm + g + 8) * AS_STRIDE + kb + tig]);
            afrag[2] = __float_as_uint(Ac[(wm + g)     * AS_STRIDE + kb + tig + 4]);
            afrag[3] = __float_as_uint(Ac[(wm + g + 8) * AS_STRIDE + kb + tig + 4]);
#pragma unroll
            for (int nt = 0; nt < 4; nt++) {
                int c = wn + nt * 8 + g;
                bfrag[nt][0] = __float_as_uint(Bc[(kb + tig)     * BS_STRIDE + c]);
                bfrag[nt][1] = __float_as_uint(Bc[(kb + tig + 4) * BS_STRIDE + c]);
            }
#pragma unroll
            for (int nt = 0; nt < 4; nt++)
                asm volatile(
                    "mma.sync.aligned.m16n8k8.row.col.f32.tf32.tf32.f32 "
                    "{%0,%1,%2,%3},{%4,%5,%6,%7},{%8,%9},{%0,%1,%2,%3};"
                    : "+f"(d[nt][0]), "+f"(d[nt][1]), "+f"(d[nt][2]), "+f"(d[nt][3])
                    : "r"(afrag[0]), "r"(afrag[1]), "r"(afrag[2]), "r"(afrag[3]),
                      "r"(bfrag[nt][0]), "r"(bfrag[nt][1]));
        }

        if (it + 2 < nIter) {
            int k0 = (it + 2) * 32;
            issueA(ws, k0);
            issueB(ws, k0);
        }
        asm volatile("cp.async.commit_group;");

        cs = (cs == 2) ? 0 : cs + 1;
        ws = (ws == 2) ? 0 : ws + 1;
    }

    // epilogue
#pragma unroll
    for (int nt = 0; nt < 4; nt++) {
        int c = n0 + wn + nt * 8 + 2 * tig;
        float b0 = bias[c], b1 = bias[c + 1];
#pragma unroll
        for (int h = 0; h < 2; h++) {
            int r = m0 + wm + g + h * 8;
            if (r >= M) continue;
            float v0 = d[nt][2 * h + 0] + b0;
            float v1 = d[nt][2 * h + 1] + b1;
            if (GELU) {
                v0 = 0.5f * v0 * (1.f + erff(v0 * 0.70710678118654752f));
                v1 = 0.5f * v1 * (1.f + erff(v1 * 0.70710678118654752f));
            }
            *(float2*)(C + (long)r * N + c) = make_float2(v0, v1);
        }
    }
}

// ---------------------------------------------------------------------------
extern "C" void kernel_launch(void* const* d_in, const int* in_sizes, int n_in,
                              void* d_out, int out_size)
{
    const float* q       = (const float*)d_in[0];
    const float* feats   = (const float*)d_in[1];
    const unsigned char* kmask = (const unsigned char*)d_in[2];
    const float* ds      = (const float*)d_in[3];
    const float* w_ref   = (const float*)d_in[4];
    const float* b_ref   = (const float*)d_in[5];
    const float* w_delta = (const float*)d_in[6];
    const float* b_delta = (const float*)d_in[7];
    const float* w_alpha = (const float*)d_in[8];
    const float* b_alpha = (const float*)d_in[9];
    const float* lam     = (const float*)d_in[10];
    const float* w_proj  = (const float*)d_in[11];
    const float* b_proj  = (const float*)d_in[12];
    const float* ln1g    = (const float*)d_in[13];
    const float* ln1b    = (const float*)d_in[14];
    const float* ln2g    = (const float*)d_in[15];
    const float* ln2b    = (const float*)d_in[16];
    const float* w_ffn1  = (const float*)d_in[17];
    const float* b_ffn1  = (const float*)d_in[18];
    const float* w_ffn2  = (const float*)d_in[19];
    const float* b_ffn2  = (const float*)d_in[20];
    const float* w_rel   = (const float*)d_in[21];
    const float* b_rel   = (const float*)d_in[22];
    float* out = (float*)d_out;

    float *pAGG, *pH, *pG, *pWc, *pbc;
    cudaGetSymbolAddress((void**)&pAGG,  g_AGG);
    cudaGetSymbolAddress((void**)&pH,    g_H);
    cudaGetSymbolAddress((void**)&pG,    g_G);
    cudaGetSymbolAddress((void**)&pWc,   g_Wc);
    cudaGetSymbolAddress((void**)&pbc,   g_bc);

    // PDL launch config (programmatic stream serialization)
    cudaLaunchAttribute pdlAttr[1];
    pdlAttr[0].id = cudaLaunchAttributeProgrammaticStreamSerialization;
    pdlAttr[0].val.programmaticStreamSerializationAllowed = 1;
    cudaLaunchConfig_t cfg = {};
    cfg.attrs = pdlAttr;
    cfg.numAttrs = 1;
    cfg.stream = 0;

    // 1) fold w_rel into the delta/alpha projections (normal launch)
    precomp_kernel<<<65, 256>>>(w_rel, b_rel, w_delta, b_delta, w_alpha, b_alpha, pWc, pbc);

    // 2) fused LN1+param+dedup+gather -> AGG[1200,256]; PDL: LN1/ref/PE
    //    overlap precomp, grid_dep_wait before consuming Wc/bc.
    cfg.gridDim = dim3(NROW, 1, 1);
    cfg.blockDim = dim3(256, 1, 1);
    cudaLaunchKernelEx(&cfg, deform_kernel,
                       q, (const float4*)feats, kmask, ds, w_ref, b_ref,
                       w_delta, w_alpha, lam, ln1g, ln1b,
                       (const float*)pWc, (const float*)pbc, (float4*)pAGG);

    // 3) out = q + AGG @ w_proj + b_proj; PDL: prefetch w_proj during deform
    cfg.gridDim = dim3(75, 4, 1);
    cfg.blockDim = dim3(128, 1, 1);
    cudaLaunchKernelEx(&cfg, tgemm_k<false, false, true>,
                       (const float*)pAGG, w_proj, b_proj, q, out,
                       (int)NROW, (int)ND, (int)ND, (int)ND);

    // 4) H = LN2(out); PDL: launch overhead overlaps proj's drain
    cfg.gridDim = dim3(NROW / 16, 1, 1);
    cfg.blockDim = dim3(512, 1, 1);
    cudaLaunchKernelEx(&cfg, ln2_kernel, (const float*)out, ln2g, ln2b, pH);

    // 5) G = gelu(H @ w_ffn1 + b_ffn1); BM=32 tile (halved B traffic);
    //    PDL: prefetch w_ffn1 during ln2
    cfg.gridDim = dim3(38, 16, 1);
    cfg.blockDim = dim3(128, 1, 1);
    cudaLaunchKernelEx(&cfg, tgemm32_k<true>,
                       (const float*)pH, w_ffn1, b_ffn1, pG,
                       (int)NROW, (int)(4 * ND), (int)ND, (int)ND);

    // 6) out += G @ w_ffn2 + b_ffn2, split-K x4 (float2 atomics);
    //    PDL: prefetch w_ffn2 slice
    cfg.gridDim = dim3(75, 4, 4);
    cfg.blockDim = dim3(128, 1, 1);
    cudaLaunchKernelEx(&cfg, tgemm_k<false, true, false>,
                       (const float*)pG, w_ffn2, b_ffn2, (const float*)nullptr, out,
                       (int)NROW, (int)ND, (int)ND, (int)(4 * ND));
}